// round 17
// baseline (speedup 1.0000x reference)
#include <cuda_runtime.h>
#include <cuda_fp16.h>
#include <cstdint>

#define NN 50000
#define EE 800000
#define D  128
#define L  3

// ---------------- scratch (device globals; no allocation APIs) ----------------
__device__ float    g_hf [NN * D];          // pre-BN layer output, fp32 (exact for BN)
__device__ uint32_t g_x16a[NN * 64];        // post-BN post-relu x, half2-packed (ping)
__device__ uint32_t g_x16b[NN * 64];        // (pong)
__device__ int   g_deg[NN];
__device__ int   g_off[NN + 1];
__device__ int   g_cur[NN];
__device__ int   g_csr[EE];                 // packed: src | et<<17 | nt(src)<<19
__device__ float g_sum[3 * D];              // per-layer BN stats
__device__ float g_ss [3 * D];
__device__ uint32_t g_wh[8 * 128 * 64];     // W split hi: [w][n][kpair] bf16x2
__device__ uint32_t g_wl[8 * 128 * 64];     // W split lo
__device__ int g_ticket;                    // decoupled-lookback scan state
__device__ unsigned long long g_scanstate[64];

__device__ __forceinline__ uint32_t* xbuf(int s) {
    return s == 0 ? g_x16a : g_x16b;
}

// pack two floats into bf16x2 (v0 low half / v1 high half) + residual pair
__device__ __forceinline__ void bf16_split2(float v0, float v1, uint32_t& hi, uint32_t& lo) {
    uint32_t h;
    asm("cvt.rn.bf16x2.f32 %0, %1, %2;" : "=r"(h) : "f"(v1), "f"(v0));
    float h0 = __uint_as_float(h << 16);
    float h1 = __uint_as_float(h & 0xFFFF0000u);
    float r0 = v0 - h0;
    float r1 = v1 - h1;
    uint32_t l;
    asm("cvt.rn.bf16x2.f32 %0, %1, %2;" : "=r"(l) : "f"(r1), "f"(r0));
    hi = h; lo = l;
}

// half2 pack/unpack
__device__ __forceinline__ uint32_t f2toh2(float x, float y) {
    __half2 h = __floats2half2_rn(x, y);
    return *reinterpret_cast<uint32_t*>(&h);
}
__device__ __forceinline__ float4 h2tof4(uint2 pq) {
    __half2 a = *reinterpret_cast<__half2*>(&pq.x);
    __half2 b = *reinterpret_cast<__half2*>(&pq.y);
    float2 fa = __half22float2(a);
    float2 fb = __half22float2(b);
    return make_float4(fa.x, fa.y, fb.x, fb.y);
}

__device__ __forceinline__ void mma16(float* c, const uint32_t* a, const uint32_t* b) {
    asm volatile("mma.sync.aligned.m16n8k16.row.col.f32.bf16.bf16.f32 "
                 "{%0,%1,%2,%3}, {%4,%5,%6,%7}, {%8,%9}, {%0,%1,%2,%3};"
                 : "+f"(c[0]), "+f"(c[1]), "+f"(c[2]), "+f"(c[3])
                 : "r"(a[0]), "r"(a[1]), "r"(a[2]), "r"(a[3]), "r"(b[0]), "r"(b[1]));
}

// ---------------- weight pre-split + all-state zero (runs FIRST) ----------------
__global__ void k_wsplit(const float* __restrict__ W1, const float* __restrict__ W2,
                         const float* __restrict__ hW1, const float* __restrict__ hW2,
                         int n) {
    int idx = blockIdx.x * blockDim.x + threadIdx.x;
    if (idx < n) g_deg[idx] = 0;
    if (idx < 3 * D) { g_sum[idx] = 0.f; g_ss[idx] = 0.f; }
    if (idx < 64) g_scanstate[idx] = 0ull;
    if (idx == 0) g_ticket = 0;
    if (idx >= 8 * 128 * 64) return;
    int w = idx >> 13;
    int nn = (idx >> 6) & 127;
    int i = idx & 63;
    const float* W;
    if (w < 6) W = ((w & 1) ? W2 : W1) + (w >> 1) * D * D;
    else W = (w == 6) ? hW1 : hW2;
    float v0 = W[(2 * i) * D + nn];
    float v1 = W[(2 * i + 1) * D + nn];
    uint32_t h, l;
    bf16_split2(v0, v1, h, l);
    g_wh[idx] = h;
    g_wl[idx] = l;
}

// ---------------- CSR build ----------------
__global__ void k_hist(const int* __restrict__ ei, int E) {
    int e = blockIdx.x * blockDim.x + threadIdx.x;
    if (e < E) atomicAdd(&g_deg[ei[E + e]], 1);
}

// single-pass decoupled-lookback exclusive scan: g_deg -> g_off, g_cur
__global__ void __launch_bounds__(256) k_scan_lb(int n, int E) {
    __shared__ int sbid;
    __shared__ int wsum[8];
    __shared__ int btot;
    __shared__ int sprefix;
    int t = threadIdx.x;
    int lane = t & 31, w = t >> 5;
    if (t == 0) sbid = atomicAdd(&g_ticket, 1);
    __syncthreads();
    int bid = sbid;
    int idx0 = bid * 1024 + t * 4;

    int v[4];
#pragma unroll
    for (int i = 0; i < 4; i++) v[i] = (idx0 + i < n) ? g_deg[idx0 + i] : 0;
    int tsum = v[0] + v[1] + v[2] + v[3];

    int s = tsum;
#pragma unroll
    for (int o = 1; o < 32; o <<= 1) {
        int x = __shfl_up_sync(0xFFFFFFFFu, s, o);
        if (lane >= o) s += x;
    }
    if (lane == 31) wsum[w] = s;
    __syncthreads();
    if (w == 0 && lane < 8) {
        int x = wsum[lane];
        int ss = x;
#pragma unroll
        for (int o = 1; o < 8; o <<= 1) {
            int y = __shfl_up_sync(0xFFu, ss, o);
            if (lane >= o) ss += y;
        }
        wsum[lane] = ss - x;
    }
    __syncthreads();
    int exclBlk = wsum[w] + s - tsum;
    if (t == 255) btot = exclBlk + tsum;
    __syncthreads();

    if (t == 0) {
        unsigned long long pkt = ((bid == 0) ? (2ull << 32) : (1ull << 32))
                               | (unsigned long long)(unsigned)btot;
        atomicExch(&g_scanstate[bid], pkt);
    }
    int prefix = 0;
    if (bid > 0) {
        if (t == 0) {
            int acc = 0;
            int j = bid - 1;
            while (true) {
                unsigned long long pkt;
                do { pkt = atomicAdd(&g_scanstate[j], 0ull); } while ((pkt >> 32) == 0ull);
                acc += (int)(unsigned)pkt;
                if ((pkt >> 32) == 2ull) break;
                j--;
            }
            sprefix = acc;
            atomicExch(&g_scanstate[bid],
                       (2ull << 32) | (unsigned long long)(unsigned)(acc + btot));
        }
        __syncthreads();
        prefix = sprefix;
    }

    int run = prefix + exclBlk;
#pragma unroll
    for (int i = 0; i < 4; i++) {
        int idx = idx0 + i;
        if (idx < n) { g_off[idx] = run; g_cur[idx] = run; }
        run += v[i];
    }
    if (bid == 0 && t == 0) g_off[n] = E;
}

// fill also packs node_type[src] (2 bits) so layer-0 gather needs no feature loads
__global__ void k_fill(const int* __restrict__ ei, const int* __restrict__ et,
                       const int* __restrict__ nt, int E) {
    int e = blockIdx.x * blockDim.x + threadIdx.x;
    if (e >= E) return;
    int src = ei[e];
    int dst = ei[E + e];
    int p = atomicAdd(&g_cur[dst], 1);
    g_csr[p] = src | (et[e] << 17) | (nt[src] << 19);
}

// ---------------- BN apply: x16 = relu(BN(h)) packed half2 ----------------
// Reads exact fp32 h (no quantized value ever passes through mean subtraction).
__global__ void k_bnapply(const float* __restrict__ gamma, const float* __restrict__ beta,
                          int statsIdx, int M, int outSel) {
    uint32_t* xOut = xbuf(outSel);
    int i = blockIdx.x * blockDim.x + threadIdx.x;    // half2 units
    if (i >= M * 64) return;
    int col = (i & 63) * 2;
    float invM = 1.f / (float)M;
    int sb = statsIdx * D;
    float mu0 = g_sum[sb + col] * invM;
    float mu1 = g_sum[sb + col + 1] * invM;
    float v0 = g_ss[sb + col] * invM - mu0 * mu0;
    float v1 = g_ss[sb + col + 1] * invM - mu1 * mu1;
    float a0 = gamma[col] * rsqrtf(v0 + 1e-5f);
    float a1 = gamma[col + 1] * rsqrtf(v1 + 1e-5f);
    float2 h = *(const float2*)&g_hf[(size_t)i * 2];
    float x0 = fmaxf((h.x - mu0) * a0 + beta[col], 0.f);
    float x1 = fmaxf((h.y - mu1) * a1 + beta[col + 1], 0.f);
    xOut[i] = f2toh2(x0, x1);
}

// ---------------- shared GEMM pieces ----------------
#define SWPAD 68
#define GEMM_SMEM ((64 + 64 + 128 + 128) * SWPAD * 4)   // Ahi, Alo, Whs, Wls

__device__ __forceinline__ void mlp_mainloop(const uint32_t* Ahi, const uint32_t* Alo,
                                             const uint32_t* Whs, const uint32_t* Wls,
                                             float acc[2][4][4],
                                             int wr, int wc, int lr, int lc) {
#pragma unroll
    for (int s = 0; s < 8; s++) {
        int kp = 8 * s + lc;
        uint32_t ah[2][4], al[2][4];
#pragma unroll
        for (int m = 0; m < 2; m++) {
            int r0 = (wr + m * 16 + lr) * SWPAD;
            int r1 = r0 + 8 * SWPAD;
            ah[m][0] = Ahi[r0 + kp];
            ah[m][1] = Ahi[r1 + kp];
            ah[m][2] = Ahi[r0 + kp + 4];
            ah[m][3] = Ahi[r1 + kp + 4];
            al[m][0] = Alo[r0 + kp];
            al[m][1] = Alo[r1 + kp];
            al[m][2] = Alo[r0 + kp + 4];
            al[m][3] = Alo[r1 + kp + 4];
        }
        uint32_t bh[4][2], bl[4][2];
#pragma unroll
        for (int n = 0; n < 4; n++) {
            int col = (wc + n * 8 + lr) * SWPAD + kp;
            bh[n][0] = Whs[col];
            bh[n][1] = Whs[col + 4];
            bl[n][0] = Wls[col];
            bl[n][1] = Wls[col + 4];
        }
#pragma unroll
        for (int m = 0; m < 2; m++)
#pragma unroll
            for (int n = 0; n < 4; n++) {
                mma16(acc[m][n], ah[m], bh[n]);
                mma16(acc[m][n], ah[m], bl[n]);
                mma16(acc[m][n], al[m], bh[n]);
            }
    }
}

__device__ __forceinline__ void stage_w(uint32_t* Whs, uint32_t* Wls, int wIdx, int tid) {
    const uint32_t* wh = g_wh + wIdx * 8192;
    const uint32_t* wl = g_wl + wIdx * 8192;
    for (int j = tid; j < 8192; j += 256) {
        int nrow = j >> 6, i = j & 63;
        Whs[nrow * SWPAD + i] = wh[j];
        Wls[nrow * SWPAD + i] = wl[j];
    }
}

// ---------------- fused GINE layer: gather+combine staged straight into MLP ----------------
// MODE 0: source feats = node_emb[node_type] in regs. MODE 1: gather post-BN x (fp16, no math).
// Then h = (relu(A@WA+bA))@WB + bB  written fp32 to g_hf, + column stats.
template <int MODE>
__global__ void __launch_bounds__(256, 2) k_fused(
        int xSel, int wIdxA, int wIdxB,
        const float* __restrict__ bA, const float* __restrict__ bB, int M,
        int statsOut,
        const float* __restrict__ eemb, const float* __restrict__ epsv, int l,
        const int* __restrict__ nt, const float* __restrict__ nemb) {
    extern __shared__ uint32_t smu[];
    uint32_t* Ahi = smu;                       // [64][SWPAD]
    uint32_t* Alo = Ahi + 64 * SWPAD;
    uint32_t* Whs = Alo + 64 * SWPAD;          // [128][SWPAD]
    uint32_t* Wls = Whs + 128 * SWPAD;

    const uint32_t* xIn = xbuf(xSel);
    int tid = threadIdx.x;
    int wid = tid >> 5;
    int lane = tid & 31;
    int row0 = blockIdx.x * 64;

    stage_w(Whs, Wls, wIdxA, tid);

    // per-lane constants
    float4 e0 = *(const float4*)&eemb[lane * 4];
    float4 e1 = *(const float4*)&eemb[D + lane * 4];
    float4 e2 = *(const float4*)&eemb[2 * D + lane * 4];
    float ep = 1.f + epsv[l];
    float4 nr0, nr1, nr2, nr3;
    if (MODE == 0) {
        nr0 = *(const float4*)&nemb[lane * 4];
        nr1 = *(const float4*)&nemb[D + lane * 4];
        nr2 = *(const float4*)&nemb[2 * D + lane * 4];
        nr3 = *(const float4*)&nemb[3 * D + lane * 4];
    }

#define NSEL(T) ((T) == 0 ? nr0 : (T) == 1 ? nr1 : (T) == 2 ? nr2 : nr3)
#define GETV(V, P) do { \
        if (MODE == 0) { int tn = ((P) >> 19) & 3; V = NSEL(tn); } \
        else { \
            uint2 pq = *(const uint2*)&xIn[(size_t)((P) & 0x1FFFF) * 64 + lane * 2]; \
            V = h2tof4(pq); } } while (0)
#define ACCE(A, V, P) do { \
        int te = ((P) >> 17) & 3; \
        float4 ev = (te == 0) ? e0 : (te == 1) ? e1 : e2; \
        A.x += fmaxf(V.x + ev.x, 0.f); \
        A.y += fmaxf(V.y + ev.y, 0.f); \
        A.z += fmaxf(V.z + ev.z, 0.f); \
        A.w += fmaxf(V.w + ev.w, 0.f); } while (0)

    // gather+combine 8 nodes per warp, write pre-split into Ahi/Alo.
    // 4-deep software unroll with scoped temporaries (keeps register pressure under
    // the 128-reg/2-CTA cap; loads within a group still issue back-to-back).
    for (int r8 = 0; r8 < 8; r8++) {
        int r = wid * 8 + r8;
        int node = row0 + r;
        float4 o = make_float4(0.f, 0.f, 0.f, 0.f);
        if (node < M) {
            float4 a0 = make_float4(0.f, 0.f, 0.f, 0.f);
            float4 a1 = make_float4(0.f, 0.f, 0.f, 0.f);
            float4 a2 = make_float4(0.f, 0.f, 0.f, 0.f);
            float4 a3 = make_float4(0.f, 0.f, 0.f, 0.f);
            int s = g_off[node], e = g_off[node + 1];
            for (int base = s; base < e; base += 32) {
                int cnt = min(32, e - base);
                int p = (lane < cnt) ? g_csr[base + lane] : 0;
                int j = 0;
                for (; j + 3 < cnt; j += 4) {
                    int p0 = __shfl_sync(0xFFFFFFFFu, p, j);
                    int p1 = __shfl_sync(0xFFFFFFFFu, p, j + 1);
                    int p2 = __shfl_sync(0xFFFFFFFFu, p, j + 2);
                    int p3 = __shfl_sync(0xFFFFFFFFu, p, j + 3);
                    float4 v0, v1, v2, v3;
                    GETV(v0, p0); GETV(v1, p1); GETV(v2, p2); GETV(v3, p3);
                    ACCE(a0, v0, p0);
                    ACCE(a1, v1, p1);
                    ACCE(a2, v2, p2);
                    ACCE(a3, v3, p3);
                }
                for (; j < cnt; j++) {
                    int p0 = __shfl_sync(0xFFFFFFFFu, p, j);
                    float4 v0;
                    GETV(v0, p0);
                    ACCE(a0, v0, p0);
                }
            }
            float4 xm;
            if (MODE == 0) {
                int tn = nt[node];
                xm = NSEL(tn);
            } else {
                uint2 pq = *(const uint2*)&xIn[(size_t)node * 64 + lane * 2];
                xm = h2tof4(pq);
            }
            o.x = ep * xm.x + (a0.x + a1.x) + (a2.x + a3.x);
            o.y = ep * xm.y + (a0.y + a1.y) + (a2.y + a3.y);
            o.z = ep * xm.z + (a0.z + a1.z) + (a2.z + a3.z);
            o.w = ep * xm.w + (a0.w + a1.w) + (a2.w + a3.w);
        }
        uint32_t h0, l0, h1, l1;
        bf16_split2(o.x, o.y, h0, l0);
        bf16_split2(o.z, o.w, h1, l1);
        int base = r * SWPAD + 2 * lane;
        Ahi[base] = h0; Ahi[base + 1] = h1;
        Alo[base] = l0; Alo[base + 1] = l1;
    }
#undef ACCE
#undef GETV
#undef NSEL
    __syncthreads();

    const int wr = (wid & 1) * 32;
    const int wc = (wid >> 1) * 32;
    const int lr = lane >> 2;
    const int lc = lane & 3;

    float acc[2][4][4];
#pragma unroll
    for (int m = 0; m < 2; m++)
#pragma unroll
        for (int n = 0; n < 4; n++)
#pragma unroll
            for (int q = 0; q < 4; q++) acc[m][n][q] = 0.f;

    mlp_mainloop(Ahi, Alo, Whs, Wls, acc, wr, wc, lr, lc);
    __syncthreads();

    // C1 = relu(acc + bA), pre-split -> Ahi/Alo ; restage WB
#pragma unroll
    for (int m = 0; m < 2; m++) {
        int rl = wr + m * 16 + lr;
#pragma unroll
        for (int n = 0; n < 4; n++) {
            int col = wc + n * 8 + lc * 2;
            int cp = col >> 1;
            float bx = bA[col], by = bA[col + 1];
            float x0 = fmaxf(acc[m][n][0] + bx, 0.f);
            float y0 = fmaxf(acc[m][n][1] + by, 0.f);
            float x1 = fmaxf(acc[m][n][2] + bx, 0.f);
            float y1 = fmaxf(acc[m][n][3] + by, 0.f);
            uint32_t h, l;
            bf16_split2(x0, y0, h, l);
            Ahi[rl * SWPAD + cp] = h;
            Alo[rl * SWPAD + cp] = l;
            bf16_split2(x1, y1, h, l);
            Ahi[(rl + 8) * SWPAD + cp] = h;
            Alo[(rl + 8) * SWPAD + cp] = l;
        }
    }
    stage_w(Whs, Wls, wIdxB, tid);
    __syncthreads();

#pragma unroll
    for (int m = 0; m < 2; m++)
#pragma unroll
        for (int n = 0; n < 4; n++)
#pragma unroll
            for (int q = 0; q < 4; q++) acc[m][n][q] = 0.f;

    mlp_mainloop(Ahi, Alo, Whs, Wls, acc, wr, wc, lr, lc);

    // epilogue: h = acc + bB -> g_hf (fp32) + column stats
    float ps[4][2], pss[4][2];
#pragma unroll
    for (int n = 0; n < 4; n++)
#pragma unroll
        for (int q = 0; q < 2; q++) { ps[n][q] = 0.f; pss[n][q] = 0.f; }

#pragma unroll
    for (int m = 0; m < 2; m++) {
        int row = row0 + wr + m * 16 + lr;
#pragma unroll
        for (int n = 0; n < 4; n++) {
            int col = wc + n * 8 + lc * 2;
            float bx = bB[col], by = bB[col + 1];
            if (row < M) {
                float ox = acc[m][n][0] + bx;
                float oy = acc[m][n][1] + by;
                ps[n][0] += ox; pss[n][0] += ox * ox;
                ps[n][1] += oy; pss[n][1] += oy * oy;
                *(float2*)&g_hf[(size_t)row * D + col] = make_float2(ox, oy);
            }
            if (row + 8 < M) {
                float ox = acc[m][n][2] + bx;
                float oy = acc[m][n][3] + by;
                ps[n][0] += ox; pss[n][0] += ox * ox;
                ps[n][1] += oy; pss[n][1] += oy * oy;
                *(float2*)&g_hf[(size_t)(row + 8) * D + col] = make_float2(ox, oy);
            }
        }
    }

    {
        int sb = statsOut * D;
#pragma unroll
        for (int n = 0; n < 4; n++)
#pragma unroll
            for (int q = 0; q < 2; q++) {
#pragma unroll
                for (int off = 4; off < 32; off <<= 1) {
                    ps[n][q]  += __shfl_xor_sync(0xFFFFFFFFu, ps[n][q], off);
                    pss[n][q] += __shfl_xor_sync(0xFFFFFFFFu, pss[n][q], off);
                }
            }
        if (lr == 0) {
#pragma unroll
            for (int n = 0; n < 4; n++) {
                int col = wc + n * 8 + lc * 2;
                atomicAdd(&g_sum[sb + col], ps[n][0]);
                atomicAdd(&g_sum[sb + col + 1], ps[n][1]);
                atomicAdd(&g_ss[sb + col], pss[n][0]);
                atomicAdd(&g_ss[sb + col + 1], pss[n][1]);
            }
        }
    }
}

// ---------------- head: reads post-BN x (fp16), 2-GEMM MLP, fused final dot ----------------
__global__ void __launch_bounds__(256, 2) k_head(
        int xSel, int wIdxA, int wIdxB,
        const float* __restrict__ bA, const float* __restrict__ bB, int M,
        const float* __restrict__ w3, const float* __restrict__ b3,
        float* __restrict__ out) {
    extern __shared__ uint32_t smu[];
    uint32_t* Ahi = smu;
    uint32_t* Alo = Ahi + 64 * SWPAD;
    uint32_t* Whs = Alo + 64 * SWPAD;
    uint32_t* Wls = Whs + 128 * SWPAD;

    const uint32_t* xIn = xbuf(xSel);
    int tid = threadIdx.x;
    int wid = tid >> 5;
    int lane = tid & 31;
    int row0 = blockIdx.x * 64;

    for (int i = tid; i < 2048; i += 256) {
        int r = i >> 5, q = i & 31;
        int gr = row0 + r;
        float4 v = make_float4(0.f, 0.f, 0.f, 0.f);
        if (gr < M) {
            uint2 pq = *(const uint2*)&xIn[(size_t)gr * 64 + q * 2];
            v = h2tof4(pq);
        }
        uint32_t h0, l0, h1, l1;
        bf16_split2(v.x, v.y, h0, l0);
        bf16_split2(v.z, v.w, h1, l1);
        int base = r * SWPAD + 2 * q;
        Ahi[base] = h0; Ahi[base + 1] = h1;
        Alo[base] = l0; Alo[base + 1] = l1;
    }
    stage_w(Whs, Wls, wIdxA, tid);
    __syncthreads();

    const int wr = (wid & 1) * 32;
    const int wc = (wid >> 1) * 32;
    const int lr = lane >> 2;
    const int lc = lane & 3;

    float acc[2][4][4];
#pragma unroll
    for (int m = 0; m < 2; m++)
#pragma unroll
        for (int n = 0; n < 4; n++)
#pragma unroll
            for (int q = 0; q < 4; q++) acc[m][n][q] = 0.f;

    mlp_mainloop(Ahi, Alo, Whs, Wls, acc, wr, wc, lr, lc);
    __syncthreads();

#pragma unroll
    for (int m = 0; m < 2; m++) {
        int rl = wr + m * 16 + lr;
#pragma unroll
        for (int n = 0; n < 4; n++) {
            int col = wc + n * 8 + lc * 2;
            int cp = col >> 1;
            float bx = bA[col], by = bA[col + 1];
            float x0 = fmaxf(acc[m][n][0] + bx, 0.f);
            float y0 = fmaxf(acc[m][n][1] + by, 0.f);
            float x1 = fmaxf(acc[m][n][2] + bx, 0.f);
            float y1 = fmaxf(acc[m][n][3] + by, 0.f);
            uint32_t h, l;
            bf16_split2(x0, y0, h, l);
            Ahi[rl * SWPAD + cp] = h;
            Alo[rl * SWPAD + cp] = l;
            bf16_split2(x1, y1, h, l);
            Ahi[(rl + 8) * SWPAD + cp] = h;
            Alo[(rl + 8) * SWPAD + cp] = l;
        }
    }
    stage_w(Whs, Wls, wIdxB, tid);
    __syncthreads();

#pragma unroll
    for (int m = 0; m < 2; m++)
#pragma unroll
        for (int n = 0; n < 4; n++)
#pragma unroll
            for (int q = 0; q < 4; q++) acc[m][n][q] = 0.f;

    mlp_mainloop(Ahi, Alo, Whs, Wls, acc, wr, wc, lr, lc);
    __syncthreads();

    // C2 = relu(acc + bB) into SMEM (reuse W buffers), dot with w3
    float* Cs = (float*)Whs;   // [64][132]
#pragma unroll
    for (int m = 0; m < 2; m++) {
        int rl = wr + m * 16 + lr;
#pragma unroll
        for (int n = 0; n < 4; n++) {
            int col = wc + n * 8 + lc * 2;
            float bx = bB[col], by = bB[col + 1];
            float2 o0, o1;
            o0.x = fmaxf(acc[m][n][0] + bx, 0.f);
            o0.y = fmaxf(acc[m][n][1] + by, 0.f);
            o1.x = fmaxf(acc[m][n][2] + bx, 0.f);
            o1.y = fmaxf(acc[m][n][3] + by, 0.f);
            *(float2*)&Cs[rl * 132 + col] = o0;
            *(float2*)&Cs[(rl + 8) * 132 + col] = o1;
        }
    }
    __syncthreads();
    float4 w = *(const float4*)&w3[lane * 4];
    float bias3 = b3[0];
#pragma unroll
    for (int r8 = 0; r8 < 8; r8++) {
        int row = wid * 8 + r8;
        float4 a = *(const float4*)&Cs[row * 132 + lane * 4];
        float s = a.x * w.x + a.y * w.y + a.z * w.z + a.w * w.w;
#pragma unroll
        for (int o = 16; o > 0; o >>= 1)
            s += __shfl_down_sync(0xFFFFFFFFu, s, o);
        if (lane == 0 && row0 + row < M)
            out[row0 + row] = s + bias3;
    }
}

// ---------------- launcher ----------------
extern "C" void kernel_launch(void* const* d_in, const int* in_sizes, int n_in,
                              void* d_out, int out_size) {
    const int*   node_type  = (const int*)  d_in[0];
    const int*   edge_type  = (const int*)  d_in[1];
    const int*   edge_index = (const int*)  d_in[2];
    const float* node_emb   = (const float*)d_in[3];
    const float* edge_emb   = (const float*)d_in[4];
    const float* eps        = (const float*)d_in[5];
    const float* W1         = (const float*)d_in[6];
    const float* b1         = (const float*)d_in[7];
    const float* W2         = (const float*)d_in[8];
    const float* b2         = (const float*)d_in[9];
    const float* gamma      = (const float*)d_in[10];
    const float* beta       = (const float*)d_in[11];
    const float* hW1        = (const float*)d_in[12];
    const float* hb1        = (const float*)d_in[13];
    const float* hW2        = (const float*)d_in[14];
    const float* hb2        = (const float*)d_in[15];
    const float* hW3        = (const float*)d_in[16];
    const float* hb3        = (const float*)d_in[17];
    float* out = (float*)d_out;

    int N = in_sizes[0];
    int E = in_sizes[1];
    int gTiles = (N + 63) / 64;
    int scanBlocks = (N + 1023) / 1024;
    int bnBlocks = (N * 64 + 255) / 256;

    static int smemSet = 0;
    if (!smemSet) {
        cudaFuncSetAttribute(k_fused<0>, cudaFuncAttributeMaxDynamicSharedMemorySize, GEMM_SMEM);
        cudaFuncSetAttribute(k_fused<1>, cudaFuncAttributeMaxDynamicSharedMemorySize, GEMM_SMEM);
        cudaFuncSetAttribute(k_head, cudaFuncAttributeMaxDynamicSharedMemorySize, GEMM_SMEM);
        smemSet = 1;
    }

    // prep: weight split + zero deg/stats/scan-state (runs first)
    k_wsplit<<<(8 * 128 * 64 + 255) / 256, 256>>>(W1, W2, hW1, hW2, N);

    // CSR build: hist -> single-pass lookback scan -> fill
    k_hist<<<(E + 255) / 256, 256>>>(edge_index, E);
    k_scan_lb<<<scanBlocks, 256>>>(N, E);
    k_fill<<<(E + 255) / 256, 256>>>(edge_index, edge_type, node_type, E);

    // layers: fused gather+MLP -> h fp32 + stats; then BN-apply -> x fp16 (ping-pong by sel)
    k_fused<0><<<gTiles, 256, GEMM_SMEM>>>(0, 0, 1, b1, b2, N, 0,
                                           edge_emb, eps, 0, node_type, node_emb);
    k_bnapply<<<bnBlocks, 256>>>(gamma, beta, 0, N, 0);

    k_fused<1><<<gTiles, 256, GEMM_SMEM>>>(0, 2, 3, b1 + D, b2 + D, N, 1,
                                           edge_emb, eps, 1, nullptr, nullptr);
    k_bnapply<<<bnBlocks, 256>>>(gamma + D, beta + D, 1, N, 1);

    k_fused<1><<<gTiles, 256, GEMM_SMEM>>>(1, 4, 5, b1 + 2 * D, b2 + 2 * D, N, 2,
                                           edge_emb, eps, 2, nullptr, nullptr);
    k_bnapply<<<bnBlocks, 256>>>(gamma + 2 * D, beta + 2 * D, 2, N, 0);

    k_head<<<gTiles, 256, GEMM_SMEM>>>(0, 6, 7, hb1, hb2, N, hW3, hb3, out);
}